// round 5
// baseline (speedup 1.0000x reference)
#include <cuda_runtime.h>

#define T_STEPS 1024
#define HID     64
#define NG      256           // 4*HID gate columns
#define NB      4             // batches per block = 2 pairs
#define NTH     320           // 256 gate/EW threads + 2 layer-2 warps

typedef unsigned long long u64;

// packed f32x2 ops (sm_103a, PTX-only)
#define FMA2(d, a, b) asm("fma.rn.f32x2 %0, %1, %2, %0;" : "+l"(d) : "l"(a), "l"(b))
#define ADD2(d, a, b) asm("add.rn.f32x2 %0, %1, %2;"     : "=l"(d) : "l"(a), "l"(b))

__device__ __forceinline__ u64 pack2(float lo, float hi) {
    u64 r;
    asm("mov.b64 %0, {%1, %2};" : "=l"(r) : "f"(lo), "f"(hi));
    return r;
}

__device__ __forceinline__ float sigm(float x) {
    return __fdividef(1.0f, 1.0f + __expf(-x));
}
__device__ __forceinline__ float tanh_f(float x) {
    float e = __expf(-2.0f * fabsf(x));            // e in (0,1], no overflow
    return copysignf(__fdividef(1.0f - e, 1.0f + e), x);
}

// gate matvec for one pair: 65 FFMA2 over 4 accumulator chains
#define GATE_PHASE(PAIR, T)                                                 \
    do {                                                                    \
        u64 a0 = bgp, a1 = 0ULL, a2 = 0ULL, a3 = 0ULL;                      \
        FMA2(a0, sxp[PAIR][T], wp[0]);                                      \
        const ulonglong2* hv = (const ulonglong2*)sh[PAIR];                 \
        _Pragma("unroll")                                                   \
        for (int k = 0; k < 16; k++) {                                      \
            ulonglong2 v  = hv[2 * k];         /* broadcast LDS.128 */      \
            ulonglong2 v2 = hv[2 * k + 1];                                  \
            FMA2(a0, v.x,  wp[4 * k + 1]);                                  \
            FMA2(a1, v.y,  wp[4 * k + 2]);                                  \
            FMA2(a2, v2.x, wp[4 * k + 3]);                                  \
            FMA2(a3, v2.y, wp[4 * k + 4]);                                  \
        }                                                                   \
        u64 s0, s1, s2;                                                     \
        ADD2(s0, a0, a1); ADD2(s1, a2, a3); ADD2(s2, s0, s1);               \
        sg[PAIR][tid] = s2;                                                 \
    } while (0)

// elementwise LSTM update for one (n, batch-half) item of a pair
#define EW_PHASE(PAIR, C1)                                                  \
    do {                                                                    \
        const float* gp = (const float*)sg[PAIR];                           \
        float gi = gp[2 * en + half];                                       \
        float gj = gp[2 * (HID     + en) + half];                           \
        float gf = gp[2 * (2 * HID + en) + half];                           \
        float go = gp[2 * (3 * HID + en) + half];                           \
        float c  = (C1) * sigm(gf + 1.0f) + sigm(gi) * tanh_f(gj);          \
        (C1) = c;                                                           \
        ((float*)sh[PAIR])[2 * en + half] = tanh_f(c) * sigm(go);           \
    } while (0)

// layer-2 LSTM (hidden=1) for one pair (2 batches), full warp
#define L2_STEP(PAIR, TOUT)                                                 \
    do {                                                                    \
        float4 hv = ((const float4*)sh[PAIR])[lane];                        \
        float ga[4], gb[4];                                                 \
        _Pragma("unroll")                                                   \
        for (int g = 0; g < 4; g++) {                                       \
            ga[g] = fmaf(hv.x, w2x[g], hv.z * w2y[g]);  /* even batch */    \
            gb[g] = fmaf(hv.y, w2x[g], hv.w * w2y[g]);  /* odd batch  */    \
        }                                                                   \
        _Pragma("unroll")                                                   \
        for (int m = 16; m >= 1; m >>= 1) {                                 \
            _Pragma("unroll")                                               \
            for (int g = 0; g < 4; g++) {                                   \
                ga[g] += __shfl_xor_sync(0xffffffffu, ga[g], m);            \
                gb[g] += __shfl_xor_sync(0xffffffffu, gb[g], m);            \
            }                                                               \
        }                                                                   \
        _Pragma("unroll")                                                   \
        for (int g = 0; g < 4; g++) {                                       \
            ga[g] += bb2[g] + h2a * w2h[g];                                 \
            gb[g] += bb2[g] + h2b * w2h[g];                                 \
        }                                                                   \
        c2a = c2a * sigm(ga[2] + 1.0f) + sigm(ga[0]) * tanh_f(ga[1]);       \
        h2a = tanh_f(c2a) * sigm(ga[3]);                                    \
        c2b = c2b * sigm(gb[2] + 1.0f) + sigm(gb[0]) * tanh_f(gb[1]);       \
        h2b = tanh_f(c2b) * sigm(gb[3]);                                    \
        if (lane == 0) {                                                    \
            outb[(size_t)(2 * (PAIR))     * T_STEPS + (TOUT)] = h2a;        \
            outb[(size_t)(2 * (PAIR) + 1) * T_STEPS + (TOUT)] = h2b;        \
        }                                                                   \
    } while (0)

__global__ __launch_bounds__(NTH, 1)
void lstm2_kernel(const float* __restrict__ x,
                  const float* __restrict__ W1,
                  const float* __restrict__ b1,
                  const float* __restrict__ W2,
                  const float* __restrict__ b2,
                  float* __restrict__ out)
{
    __shared__ __align__(16) u64 sxp[2][T_STEPS];  // x, pair-packed
    __shared__ __align__(16) u64 sh[2][HID];       // h1 per pair (single-buffered)
    __shared__ __align__(16) u64 sg[2][NG];        // gate pre-activations per pair

    const int tid  = threadIdx.x;
    const int base = blockIdx.x * NB;

    for (int i = tid; i < 2 * T_STEPS; i += NTH) {
        int p = i >> 10, t = i & (T_STEPS - 1);
        sxp[p][t] = pack2(x[(size_t)(base + 2 * p)     * T_STEPS + t],
                          x[(size_t)(base + 2 * p + 1) * T_STEPS + t]);
    }
    if (tid < 2 * HID) sh[tid >> 6][tid & 63] = 0ULL;

    // gate weights: one W1 column, duplicated into f32x2 (shared by both pairs)
    u64 wp[65];
    u64 bgp = 0ULL;
    if (tid < NG) {
        #pragma unroll
        for (int k = 0; k < 65; k++) {
            float w = W1[k * NG + tid];
            wp[k] = pack2(w, w);
        }
        float bg = b1[tid];
        bgp = pack2(bg, bg);
    }

    // elementwise ownership (tid < 128): item (en, half) of the active pair
    const int en = tid & 63, half = (tid >> 6) & 1;
    float c1A = 0.0f, c1B = 0.0f;

    // layer-2 warps: warp 8 -> pair 0, warp 9 -> pair 1
    const int wid  = tid >> 5;
    const int lane = tid & 31;
    float w2x[4], w2y[4], w2h[4], bb2[4];
    float c2a = 0.0f, h2a = 0.0f, c2b = 0.0f, h2b = 0.0f;
    if (wid >= 8) {
        #pragma unroll
        for (int g = 0; g < 4; g++) {
            w2x[g] = W2[(2 * lane)     * 4 + g];
            w2y[g] = W2[(2 * lane + 1) * 4 + g];
            w2h[g] = W2[64 * 4 + g];
            bb2[g] = b2[g];
        }
    }
    __syncthreads();

    float* outb = out + (size_t)base * T_STEPS;

    for (int t = 0; t < T_STEPS; t++) {
        // ---- phase A: gates(pair0, t)  ||  EW(pair1, t-1)  ||  L2 pair0 ----
        if (tid < NG) {
            GATE_PHASE(0, t);
            if (tid < 128 && t > 0) EW_PHASE(1, c1B);
        } else if (wid == 8 && t > 0) {
            L2_STEP(0, t - 1);
        }
        __syncthreads();

        // ---- phase B: gates(pair1, t)  ||  EW(pair0, t)    ||  L2 pair1 ----
        if (tid < NG) {
            GATE_PHASE(1, t);
            if (tid < 128) EW_PHASE(0, c1A);
        } else if (wid == 9 && t > 0) {
            L2_STEP(1, t - 1);
        }
        __syncthreads();
    }

    // ---- epilogue: EW(pair1, T-1), then final layer-2 steps ----
    if (tid < 128) EW_PHASE(1, c1B);
    if (wid == 8) L2_STEP(0, T_STEPS - 1);     // sh[0] = h1(pair0, T-1)
    __syncthreads();
    if (wid == 9) L2_STEP(1, T_STEPS - 1);     // sh[1] = h1(pair1, T-1)
}

extern "C" void kernel_launch(void* const* d_in, const int* in_sizes, int n_in,
                              void* d_out, int out_size)
{
    const float* x  = (const float*)d_in[0];   // [512,1024,1]
    const float* W1 = (const float*)d_in[1];   // [65,256]
    const float* b1 = (const float*)d_in[2];   // [256]
    const float* W2 = (const float*)d_in[3];   // [65,4]
    const float* b2 = (const float*)d_in[4];   // [4]
    float* out = (float*)d_out;                // [512,1024,1]

    (void)in_sizes; (void)n_in; (void)out_size;
    lstm2_kernel<<<512 / NB, NTH>>>(x, W1, b1, W2, b2, out);
}